// round 2
// baseline (speedup 1.0000x reference)
#include <cuda_runtime.h>

// Problem geometry
#define NB   2
#define NI   256
#define NJ   256
#define NK   64
#define CVOL (NI*NJ*NK)                       // 4,194,304 per (batch,channel)
#define NPIX ((double)NB*CVOL)                // 8,388,608
#define NCELL ((double)NB*255.0*255.0*63.0)   // cells
#define JSTRIP 16

__device__ double g_acc[4];   // zero-initialized at module load; finalize resets

__global__ void __launch_bounds__(256)
loss_kernel(const float* __restrict__ O, const float* __restrict__ T)
{
    const int tid  = blockIdx.x * 256 + threadIdx.x;
    const int lane = tid & 31;
    const int w    = tid >> 5;               // 8192 warps = 2*256*16
    const int b    = w >> 12;                // /4096
    const int rem  = w & 4095;
    const int i    = rem >> 4;               // 0..255
    const int js   = rem & 15;               // j-strip
    const int j0   = js * JSTRIP;
    const int jend = (j0 + JSTRIP < NJ) ? (j0 + JSTRIP) : (NJ - 1); // last row to load

    const float* __restrict__ Obx = O + (long)b * 3 * CVOL;
    const float* __restrict__ Oby = Obx + CVOL;
    const float* __restrict__ Obz = Obx + 2L * CVOL;
    const float* __restrict__ Ttx = T + (long)b * 4 * CVOL;
    const float* __restrict__ Tty = Ttx + CVOL;
    const float* __restrict__ Ttz = Ttx + 2L * CVOL;
    const float* __restrict__ Tz  = Ttx + 3L * CVOL;

    const bool valid_i = (i < NI - 1);
    const long io = valid_i ? (long)(NJ * NK) : 0;   // clamped i+1 offset

    const unsigned FULL = 0xffffffffu;
    const float DX = 0.1f, DY = 0.1f;

    float s_bxy = 0.f, s_bz = 0.f, s_par = 0.f, s_div = 0.f;

    // carried state: previous-j rows (i and i+1) + their k+2 shuffles
    float2 pbx0, pby0, pbz0, pz0, pbx1, pby1, pbz1, pz1;
    float  pbx0s, pby0s, pbz0s, pz0s, pbx1s, pby1s, pbz1s, pz1s;

    // divergence cell: corner naming f_{di}{dj}{dk}
    auto cell = [&](float bx000, float bx001, float bx010, float bx011,
                    float bx100, float bx101, float bx110, float bx111,
                    float by000, float by001, float by010, float by011,
                    float by100, float by101, float by110, float by111,
                    float bz000, float bz001, float bz010, float bz011,
                    float bz100, float bz101, float bz110, float bz111,
                    float z000,  float z001,  float z010,  float z011,
                    float z100,  float z101,  float z110,  float z111)
    {
        float num =
            0.125f*DY*( (bx100+bx110+bx101+bx111)*(z101-z100+z111-z110)
                      - (bx000+bx010+bx001+bx011)*(z001-z000+z011-z010) )
          + 0.125f*DX*( (by010+by110+by011+by111)*(z011-z010+z111-z110)
                      - (by000+by100+by001+by101)*(z001-z000+z101-z100) )
          + 0.25f*DX*DY*((bz001+bz011+bz101+bz111)-(bz000+bz010+bz100+bz110))
          + (DY/6.f)*( (bx001+bx101+bx111)*(z001-z101)
                     + (bx011+bx111+bx101)*(z011-z111)
                     - (bx000+bx100+bx110)*(z000-z100)
                     - (bx010+bx110+bx100)*(z010-z110) )
          + (DX/6.f)*( (by101+by111+by011)*(z101-z111)
                     + (by001+by011+by111)*(z001-z011)
                     - (by100+by110+by010)*(z100-z110)
                     - (by000+by010+by110)*(z000-z010) );
        float bxc = 0.125f*(bx000+bx001+bx010+bx011+bx100+bx101+bx110+bx111);
        float byc = 0.125f*(by000+by001+by010+by011+by100+by101+by110+by111);
        float bzc = 0.125f*(bz000+bz001+bz010+bz011+bz100+bz101+bz110+bz111);
        float den = bxc*bxc + byc*byc + bzc*bzc + 1e-10f;
        s_div += __fdividef(num*num, den);
    };

    long rbase = ((long)(i * NJ + j0)) * NK + 2 * lane;

    #pragma unroll 1
    for (int jr = j0; jr <= jend; ++jr, rbase += NK) {
        // ---- 8 corner-channel loads (cur rows at i and i+1) ----
        const float2 cbx0 = *(const float2*)(Obx + rbase);
        const float2 cby0 = *(const float2*)(Oby + rbase);
        const float2 cbz0 = *(const float2*)(Obz + rbase);
        const float2 cz0  = *(const float2*)(Tz  + rbase);
        const float2 cbx1 = *(const float2*)(Obx + rbase + io);
        const float2 cby1 = *(const float2*)(Oby + rbase + io);
        const float2 cbz1 = *(const float2*)(Obz + rbase + io);
        const float2 cz1  = *(const float2*)(Tz  + rbase + io);

        // ---- element-wise losses (strip-interior rows only) ----
        if (jr < j0 + JSTRIP) {
            const float2 tx = *(const float2*)(Ttx + rbase);
            const float2 ty = *(const float2*)(Tty + rbase);
            const float2 tz = *(const float2*)(Ttz + rbase);
            #pragma unroll
            for (int e = 0; e < 2; e++) {
                const float bxp = e ? cbx0.y : cbx0.x;
                const float byp = e ? cby0.y : cby0.x;
                const float bzp = e ? cbz0.y : cbz0.x;
                const float bxt = e ? tx.y : tx.x;
                const float byt = e ? ty.y : ty.x;
                const float bzt = e ? tz.y : tz.x;
                const float bxt2 = bxt*bxt, byt2 = byt*byt, bzt2 = bzt*bzt;
                const float t  = bxp*bxp + byp*byp - bxt2 - byt2;
                s_bxy += __fdividef(t*t, bxt2 + byt2 + 1e-10f);
                const float d  = bzp - bzt; const float d2 = d*d;
                s_bz  += __fdividef(d2*d2, bzt2 + 1e-10f);
                const float cr = bxp*byt - byp*bxt;
                s_par += __fdividef(cr*cr, bxt2 + byt2 + bzt2 + 1e-10f);
            }
        }

        // ---- k+2 halo shuffles for the new rows ----
        const float cbx0s = __shfl_down_sync(FULL, cbx0.x, 1);
        const float cby0s = __shfl_down_sync(FULL, cby0.x, 1);
        const float cbz0s = __shfl_down_sync(FULL, cbz0.x, 1);
        const float cz0s  = __shfl_down_sync(FULL, cz0.x,  1);
        const float cbx1s = __shfl_down_sync(FULL, cbx1.x, 1);
        const float cby1s = __shfl_down_sync(FULL, cby1.x, 1);
        const float cbz1s = __shfl_down_sync(FULL, cbz1.x, 1);
        const float cz1s  = __shfl_down_sync(FULL, cz1.x,  1);

        // ---- cells in slab (jr-1, jr) ----
        if (jr > j0 && valid_i) {
            // cell at k = 2*lane  (dk=0 -> .x, dk=1 -> .y)
            cell(pbx0.x, pbx0.y, cbx0.x, cbx0.y, pbx1.x, pbx1.y, cbx1.x, cbx1.y,
                 pby0.x, pby0.y, cby0.x, cby0.y, pby1.x, pby1.y, cby1.x, cby1.y,
                 pbz0.x, pbz0.y, cbz0.x, cbz0.y, pbz1.x, pbz1.y, cbz1.x, cbz1.y,
                 pz0.x,  pz0.y,  cz0.x,  cz0.y,  pz1.x,  pz1.y,  cz1.x,  cz1.y);
            // cell at k = 2*lane+1 (dk=0 -> .y, dk=1 -> shuffled)
            if (lane < 31) {
                cell(pbx0.y, pbx0s, cbx0.y, cbx0s, pbx1.y, pbx1s, cbx1.y, cbx1s,
                     pby0.y, pby0s, cby0.y, cby0s, pby1.y, pby1s, cby1.y, cby1s,
                     pbz0.y, pbz0s, cbz0.y, cbz0s, pbz1.y, pbz1s, cbz1.y, cbz1s,
                     pz0.y,  pz0s,  cz0.y,  cz0s,  pz1.y,  pz1s,  cz1.y,  cz1s);
            }
        }

        // rotate carried state
        pbx0 = cbx0; pby0 = cby0; pbz0 = cbz0; pz0 = cz0;
        pbx1 = cbx1; pby1 = cby1; pbz1 = cbz1; pz1 = cz1;
        pbx0s = cbx0s; pby0s = cby0s; pbz0s = cbz0s; pz0s = cz0s;
        pbx1s = cbx1s; pby1s = cby1s; pbz1s = cbz1s; pz1s = cz1s;
    }
    (void)pbx0s; (void)pby0s; (void)pbz0s; (void)pz0s;
    (void)pbx1s; (void)pby1s; (void)pbz1s; (void)pz1s;

    // ---- reduction: warp -> shared -> block -> global(double) ----
    #pragma unroll
    for (int o = 16; o; o >>= 1) {
        s_bxy += __shfl_down_sync(FULL, s_bxy, o);
        s_bz  += __shfl_down_sync(FULL, s_bz,  o);
        s_par += __shfl_down_sync(FULL, s_par, o);
        s_div += __shfl_down_sync(FULL, s_div, o);
    }
    __shared__ float sh[4][8];
    const int wrp = threadIdx.x >> 5;
    if (lane == 0) { sh[0][wrp]=s_bxy; sh[1][wrp]=s_bz; sh[2][wrp]=s_par; sh[3][wrp]=s_div; }
    __syncthreads();
    if (threadIdx.x < 4) {
        float s = 0.f;
        #pragma unroll
        for (int q = 0; q < 8; q++) s += sh[threadIdx.x][q];
        atomicAdd(&g_acc[threadIdx.x], (double)s);
    }
}

__global__ void finalize_kernel(float* __restrict__ out)
{
    const double lb = g_acc[0] / NPIX + g_acc[1] / NPIX;
    const double lp = g_acc[2] / NPIX;
    out[0] = (float)(1000.0 * lb + 1000.0 * lp);
    out[1] = (float)(100.0 * (g_acc[3] / NCELL) * 1.0e4);  // / DX^2 / DY^2
    // reset for the next graph replay (g_acc is zero at module load)
    g_acc[0] = 0.0; g_acc[1] = 0.0; g_acc[2] = 0.0; g_acc[3] = 0.0;
}

extern "C" void kernel_launch(void* const* d_in, const int* in_sizes, int n_in,
                              void* d_out, int out_size)
{
    const float* outputs = (const float*)d_in[0];
    const float* targets = (const float*)d_in[1];
    if (n_in >= 2 && in_sizes[0] == 4 * NB * CVOL && in_sizes[1] == 3 * NB * CVOL) {
        const float* t = outputs; outputs = targets; targets = t;
    }
    float* out = (float*)d_out;

    // 8192 warps: 2 batches x 256 i x 16 j-strips -> 1024 blocks x 256 threads
    loss_kernel<<<1024, 256>>>(outputs, targets);
    finalize_kernel<<<1, 1>>>(out);
}

// round 3
// speedup vs baseline: 1.2729x; 1.2729x over previous
#include <cuda_runtime.h>

// Problem geometry
#define NB   2
#define NI   256
#define NJ   256
#define NK   64
#define CVOL (NI*NJ*NK)                       // 4,194,304 per (batch,channel)
#define NPIX ((double)NB*CVOL)                // 8,388,608
#define NCELL ((double)NB*255.0*255.0*63.0)   // cells
#define GRID 16384

__device__ double   g_acc[4];    // zero at module load; last block resets
__device__ unsigned g_cnt;       // zero at module load; last block resets

__global__ void __launch_bounds__(256, 3)
loss_kernel(const float* __restrict__ O, const float* __restrict__ T,
            float* __restrict__ out)
{
    const int tid  = blockIdx.x * 256 + threadIdx.x;
    const int lane = tid & 31;
    const int row  = tid >> 5;            // 131072 rows = 2*256*256
    const int b    = row >> 16;
    const int ij   = row & 65535;
    const int i    = ij >> 8;
    const int j    = ij & 255;

    const int base = (ij << 6) + (lane << 1);          // (i*256+j)*64 + 2*lane
    const float* __restrict__ Obx = O + b * (3 * CVOL);
    const float* __restrict__ Oby = Obx + CVOL;
    const float* __restrict__ Obz = Obx + 2 * CVOL;
    const float* __restrict__ Ttx = T + b * (4 * CVOL);
    const float* __restrict__ Tty = Ttx + CVOL;
    const float* __restrict__ Ttz = Ttx + 2 * CVOL;
    const float* __restrict__ Tz  = Ttx + 3 * CVOL;

    // clamped corner offsets (loads stay in-bounds; contribution gated later)
    const int io = (i < NI - 1) ? (NJ * NK) : 0;
    const int jo = (j < NJ - 1) ? NK : 0;
    const bool valid_ij = (i < NI - 1) && (j < NJ - 1);

    const unsigned FULL = 0xffffffffu;
    const float DX = 0.1f, DY = 0.1f;

    float s_bxy = 0.f, s_bz = 0.f, s_par = 0.f, s_div = 0.f;

    // ================= phase 0: z corners (live through all phases) ========
    const float2 Z00 = *(const float2*)(Tz + base);
    const float2 Z01 = *(const float2*)(Tz + base + jo);
    const float2 Z10 = *(const float2*)(Tz + base + io);
    const float2 Z11 = *(const float2*)(Tz + base + io + jo);
    const float z00s = __shfl_down_sync(FULL, Z00.x, 1);
    const float z01s = __shfl_down_sync(FULL, Z01.x, 1);
    const float z10s = __shfl_down_sync(FULL, Z10.x, 1);
    const float z11s = __shfl_down_sync(FULL, Z11.x, 1);

    // z corner arrays per cell: order z000,z001,z010,z011,z100,z101,z110,z111
    const float z0[8] = {Z00.x, Z00.y, Z01.x, Z01.y, Z10.x, Z10.y, Z11.x, Z11.y};
    const float z1[8] = {Z00.y, z00s,  Z01.y, z01s,  Z10.y, z10s,  Z11.y, z11s};

    float num0 = 0.f, num1 = 0.f;     // divergence numerator accumulators
    float den0 = 1e-10f, den1 = 1e-10f;

    // per-channel corner term for the x-flux pieces (DY-scaled)
    auto bx_term = [&](float b000, float b001, float b010, float b011,
                       float b100, float b101, float b110, float b111,
                       const float* z) -> float {
        return 0.125f*DY*((b100+b110+b101+b111)*(z[5]-z[4]+z[7]-z[6])
                        - (b000+b010+b001+b011)*(z[1]-z[0]+z[3]-z[2]))
             + (DY/6.f)*((b001+b101+b111)*(z[1]-z[5])
                       + (b011+b111+b101)*(z[3]-z[7])
                       - (b000+b100+b110)*(z[0]-z[4])
                       - (b010+b110+b100)*(z[2]-z[6]));
    };
    auto by_term = [&](float b000, float b001, float b010, float b011,
                       float b100, float b101, float b110, float b111,
                       const float* z) -> float {
        return 0.125f*DX*((b010+b110+b011+b111)*(z[3]-z[2]+z[7]-z[6])
                        - (b000+b100+b001+b101)*(z[1]-z[0]+z[5]-z[4]))
             + (DX/6.f)*((b101+b111+b011)*(z[5]-z[7])
                       + (b001+b011+b111)*(z[1]-z[3])
                       - (b100+b110+b010)*(z[4]-z[6])
                       - (b000+b010+b110)*(z[0]-z[2]));
    };
    auto ctr = [](float b000, float b001, float b010, float b011,
                  float b100, float b101, float b110, float b111) -> float {
        return 0.125f*(b000+b001+b010+b011+b100+b101+b110+b111);
    };

    // ================= phase 1: bx =========================================
    {
        const float2 C00 = *(const float2*)(Obx + base);
        const float2 C01 = *(const float2*)(Obx + base + jo);
        const float2 C10 = *(const float2*)(Obx + base + io);
        const float2 C11 = *(const float2*)(Obx + base + io + jo);
        const float s00 = __shfl_down_sync(FULL, C00.x, 1);
        const float s01 = __shfl_down_sync(FULL, C01.x, 1);
        const float s10 = __shfl_down_sync(FULL, C10.x, 1);
        const float s11 = __shfl_down_sync(FULL, C11.x, 1);

        num0 += bx_term(C00.x, C00.y, C01.x, C01.y, C10.x, C10.y, C11.x, C11.y, z0);
        num1 += bx_term(C00.y, s00,   C01.y, s01,   C10.y, s10,   C11.y, s11,   z1);
        float c0 = ctr(C00.x, C00.y, C01.x, C01.y, C10.x, C10.y, C11.x, C11.y);
        float c1 = ctr(C00.y, s00,   C01.y, s01,   C10.y, s10,   C11.y, s11);
        den0 += c0*c0; den1 += c1*c1;

        // elementwise (bx half): needs targets tx,ty too -> deferred to phase 2
        // keep bxp values for phase: reuse C00
        const float2 tx = *(const float2*)(Ttx + base);
        const float2 ty = *(const float2*)(Tty + base);
        const float2 by0 = *(const float2*)(Oby + base);   // prefetch by base
        #pragma unroll
        for (int e = 0; e < 2; e++) {
            const float bxp = e ? C00.y : C00.x;
            const float byp = e ? by0.y : by0.x;
            const float bxt = e ? tx.y : tx.x;
            const float byt = e ? ty.y : ty.x;
            const float bxt2 = bxt*bxt, byt2 = byt*byt;
            const float t  = bxp*bxp + byp*byp - bxt2 - byt2;
            s_bxy += __fdividef(t*t, bxt2 + byt2 + 1e-10f);
            const float cr = bxp*byt - byp*bxt;
            // parallel loss needs bzt2: fold via storing partial
            // do full parallel term here with tz loaded below in phase 3? ->
            // instead load tz now (small extra live range)
            (void)cr;
            // handled below
        }
        // parallel loss with bzt: load tz here
        const float2 tz = *(const float2*)(Ttz + base);
        #pragma unroll
        for (int e = 0; e < 2; e++) {
            const float bxp = e ? C00.y : C00.x;
            const float byp = e ? by0.y : by0.x;
            const float bxt = e ? tx.y : tx.x;
            const float byt = e ? ty.y : ty.x;
            const float bzt = e ? tz.y : tz.x;
            const float cr = bxp*byt - byp*bxt;
            s_par += __fdividef(cr*cr, bxt*bxt + byt*byt + bzt*bzt + 1e-10f);
        }
        // bz elementwise: load bz base + tz
        const float2 bz0 = *(const float2*)(Obz + base);
        #pragma unroll
        for (int e = 0; e < 2; e++) {
            const float bzp = e ? bz0.y : bz0.x;
            const float bzt = e ? tz.y : tz.x;
            const float d = bzp - bzt; const float d2 = d*d;
            s_bz += __fdividef(d2*d2, bzt*bzt + 1e-10f);
        }
    }

    // ================= phase 2: by corners =================================
    {
        const float2 C00 = *(const float2*)(Oby + base);
        const float2 C01 = *(const float2*)(Oby + base + jo);
        const float2 C10 = *(const float2*)(Oby + base + io);
        const float2 C11 = *(const float2*)(Oby + base + io + jo);
        const float s00 = __shfl_down_sync(FULL, C00.x, 1);
        const float s01 = __shfl_down_sync(FULL, C01.x, 1);
        const float s10 = __shfl_down_sync(FULL, C10.x, 1);
        const float s11 = __shfl_down_sync(FULL, C11.x, 1);

        num0 += by_term(C00.x, C00.y, C01.x, C01.y, C10.x, C10.y, C11.x, C11.y, z0);
        num1 += by_term(C00.y, s00,   C01.y, s01,   C10.y, s10,   C11.y, s11,   z1);
        float c0 = ctr(C00.x, C00.y, C01.x, C01.y, C10.x, C10.y, C11.x, C11.y);
        float c1 = ctr(C00.y, s00,   C01.y, s01,   C10.y, s10,   C11.y, s11);
        den0 += c0*c0; den1 += c1*c1;
    }

    // ================= phase 3: bz corners =================================
    {
        const float2 C00 = *(const float2*)(Obz + base);
        const float2 C01 = *(const float2*)(Obz + base + jo);
        const float2 C10 = *(const float2*)(Obz + base + io);
        const float2 C11 = *(const float2*)(Obz + base + io + jo);
        const float s00 = __shfl_down_sync(FULL, C00.x, 1);
        const float s01 = __shfl_down_sync(FULL, C01.x, 1);
        const float s10 = __shfl_down_sync(FULL, C10.x, 1);
        const float s11 = __shfl_down_sync(FULL, C11.x, 1);

        const float DXY = 0.25f * DX * DY;
        num0 += DXY * ((C00.y + C01.y + C10.y + C11.y) - (C00.x + C01.x + C10.x + C11.x));
        num1 += DXY * ((s00 + s01 + s10 + s11) - (C00.y + C01.y + C10.y + C11.y));
        float c0 = ctr(C00.x, C00.y, C01.x, C01.y, C10.x, C10.y, C11.x, C11.y);
        float c1 = ctr(C00.y, s00,   C01.y, s01,   C10.y, s10,   C11.y, s11);
        den0 += c0*c0; den1 += c1*c1;
    }

    // ================= divergence accumulation =============================
    if (valid_ij) {
        s_div += __fdividef(num0*num0, den0);
        if (lane < 31) s_div += __fdividef(num1*num1, den1);
    }

    // ================= reduction ===========================================
    #pragma unroll
    for (int o = 16; o; o >>= 1) {
        s_bxy += __shfl_down_sync(FULL, s_bxy, o);
        s_bz  += __shfl_down_sync(FULL, s_bz,  o);
        s_par += __shfl_down_sync(FULL, s_par, o);
        s_div += __shfl_down_sync(FULL, s_div, o);
    }
    __shared__ float sh[4][8];
    const int wrp = threadIdx.x >> 5;
    if (lane == 0) { sh[0][wrp]=s_bxy; sh[1][wrp]=s_bz; sh[2][wrp]=s_par; sh[3][wrp]=s_div; }
    __syncthreads();
    if (threadIdx.x < 4) {
        float s = 0.f;
        #pragma unroll
        for (int q = 0; q < 8; q++) s += sh[threadIdx.x][q];
        atomicAdd(&g_acc[threadIdx.x], (double)s);
    }
    __syncthreads();

    // ================= grid-wide finalize (last block) =====================
    if (threadIdx.x == 0) {
        __threadfence();
        const unsigned ticket = atomicAdd(&g_cnt, 1u);
        if (ticket == GRID - 1) {
            __threadfence();   // acquire all g_acc updates
            const double lb = g_acc[0] / NPIX + g_acc[1] / NPIX;
            const double lp = g_acc[2] / NPIX;
            out[0] = (float)(1000.0 * lb + 1000.0 * lp);
            out[1] = (float)(100.0 * (g_acc[3] / NCELL) * 1.0e4); // / DX^2 / DY^2
            // reset for next graph replay
            g_acc[0] = 0.0; g_acc[1] = 0.0; g_acc[2] = 0.0; g_acc[3] = 0.0;
            g_cnt = 0u;
            __threadfence();
        }
    }
}

extern "C" void kernel_launch(void* const* d_in, const int* in_sizes, int n_in,
                              void* d_out, int out_size)
{
    const float* outputs = (const float*)d_in[0];
    const float* targets = (const float*)d_in[1];
    if (n_in >= 2 && in_sizes[0] == 4 * NB * CVOL && in_sizes[1] == 3 * NB * CVOL) {
        const float* t = outputs; outputs = targets; targets = t;
    }
    loss_kernel<<<GRID, 256>>>(outputs, targets, (float*)d_out);
}

// round 4
// speedup vs baseline: 1.3437x; 1.0556x over previous
#include <cuda_runtime.h>

// Problem geometry
#define NB   2
#define NI   256
#define NJ   256
#define NK   64
#define CVOL (NI*NJ*NK)                       // 4,194,304 per (batch,channel)
#define NPIX ((double)NB*CVOL)                // 8,388,608
#define NCELL ((double)NB*255.0*255.0*63.0)   // cells
#define GRID 16384

__device__ double   g_acc[4];    // zero at module load; last block resets
__device__ unsigned g_cnt;       // zero at module load; last block resets

__global__ void __launch_bounds__(256)
loss_kernel(const float* __restrict__ O, const float* __restrict__ T,
            float* __restrict__ out)
{
    const int tid  = blockIdx.x * 256 + threadIdx.x;
    const int lane = tid & 31;
    const int row  = tid >> 5;            // 131072 rows = 2*256*256
    const int b    = row >> 16;
    const int ij   = row & 65535;
    const int i    = ij >> 8;
    const int j    = ij & 255;

    const int base = (ij << 6) + (lane << 1);          // (i*256+j)*64 + 2*lane
    const float* __restrict__ Ob = O + b * (3 * CVOL);
    const float* __restrict__ Tb = T + b * (4 * CVOL);

    // clamped corner offsets (loads stay in-bounds; contribution gated below)
    const int io = (i < NI - 1) ? (NJ * NK) : 0;
    const int jo = (j < NJ - 1) ? NK : 0;

    // ---- front-batched loads: 19 x LDG.64 per thread ----
    const float2 BX00 = *(const float2*)(Ob + base);
    const float2 BX10 = *(const float2*)(Ob + base + io);
    const float2 BX01 = *(const float2*)(Ob + base + jo);
    const float2 BX11 = *(const float2*)(Ob + base + io + jo);

    const float2 BY00 = *(const float2*)(Ob + CVOL + base);
    const float2 BY10 = *(const float2*)(Ob + CVOL + base + io);
    const float2 BY01 = *(const float2*)(Ob + CVOL + base + jo);
    const float2 BY11 = *(const float2*)(Ob + CVOL + base + io + jo);

    const float2 BZ00 = *(const float2*)(Ob + 2*CVOL + base);
    const float2 BZ10 = *(const float2*)(Ob + 2*CVOL + base + io);
    const float2 BZ01 = *(const float2*)(Ob + 2*CVOL + base + jo);
    const float2 BZ11 = *(const float2*)(Ob + 2*CVOL + base + io + jo);

    const float2 Z00  = *(const float2*)(Tb + 3*CVOL + base);
    const float2 Z10  = *(const float2*)(Tb + 3*CVOL + base + io);
    const float2 Z01  = *(const float2*)(Tb + 3*CVOL + base + jo);
    const float2 Z11  = *(const float2*)(Tb + 3*CVOL + base + io + jo);

    const float2 TX   = *(const float2*)(Tb + base);
    const float2 TY   = *(const float2*)(Tb + CVOL + base);
    const float2 TZ   = *(const float2*)(Tb + 2*CVOL + base);

    // ---- batched warp-internal k+2 halos ----
    const unsigned FULL = 0xffffffffu;
    const float nbx00 = __shfl_down_sync(FULL, BX00.x, 1);
    const float nbx10 = __shfl_down_sync(FULL, BX10.x, 1);
    const float nbx01 = __shfl_down_sync(FULL, BX01.x, 1);
    const float nbx11 = __shfl_down_sync(FULL, BX11.x, 1);
    const float nby00 = __shfl_down_sync(FULL, BY00.x, 1);
    const float nby10 = __shfl_down_sync(FULL, BY10.x, 1);
    const float nby01 = __shfl_down_sync(FULL, BY01.x, 1);
    const float nby11 = __shfl_down_sync(FULL, BY11.x, 1);
    const float nbz00 = __shfl_down_sync(FULL, BZ00.x, 1);
    const float nbz10 = __shfl_down_sync(FULL, BZ10.x, 1);
    const float nbz01 = __shfl_down_sync(FULL, BZ01.x, 1);
    const float nbz11 = __shfl_down_sync(FULL, BZ11.x, 1);
    const float nz00  = __shfl_down_sync(FULL, Z00.x, 1);
    const float nz10  = __shfl_down_sync(FULL, Z10.x, 1);
    const float nz01  = __shfl_down_sync(FULL, Z01.x, 1);
    const float nz11  = __shfl_down_sync(FULL, Z11.x, 1);

    float s_bxy = 0.f, s_bz = 0.f, s_par = 0.f, s_div = 0.f;

    // ---- element-wise losses (both k values) ----
    #pragma unroll
    for (int e = 0; e < 2; e++) {
        const float bxp = e ? BX00.y : BX00.x;
        const float byp = e ? BY00.y : BY00.x;
        const float bzp = e ? BZ00.y : BZ00.x;
        const float bxt = e ? TX.y : TX.x;
        const float byt = e ? TY.y : TY.x;
        const float bzt = e ? TZ.y : TZ.x;

        const float bxt2 = bxt*bxt, byt2 = byt*byt, bzt2 = bzt*bzt;
        const float t = bxp*bxp + byp*byp - bxt2 - byt2;
        s_bxy += __fdividef(t*t, bxt2 + byt2 + 1e-10f);
        const float d = bzp - bzt; const float d2 = d*d;
        s_bz  += __fdividef(d2*d2, bzt2 + 1e-10f);
        const float cr = bxp*byt - byp*bxt;
        s_par += __fdividef(cr*cr, bxt2 + byt2 + bzt2 + 1e-10f);
    }

    // ---- divergence cells ----
    const float DX = 0.1f, DY = 0.1f;
    auto cell = [&](float bx000, float bx001, float bx010, float bx011,
                    float bx100, float bx101, float bx110, float bx111,
                    float by000, float by001, float by010, float by011,
                    float by100, float by101, float by110, float by111,
                    float bz000, float bz001, float bz010, float bz011,
                    float bz100, float bz101, float bz110, float bz111,
                    float z000,  float z001,  float z010,  float z011,
                    float z100,  float z101,  float z110,  float z111)
    {
        float num =
            0.125f*DY*( (bx100+bx110+bx101+bx111)*(z101-z100+z111-z110)
                      - (bx000+bx010+bx001+bx011)*(z001-z000+z011-z010) )
          + 0.125f*DX*( (by010+by110+by011+by111)*(z011-z010+z111-z110)
                      - (by000+by100+by001+by101)*(z001-z000+z101-z100) )
          + 0.25f*DX*DY*((bz001+bz011+bz101+bz111)-(bz000+bz010+bz100+bz110))
          + (DY/6.f)*( (bx001+bx101+bx111)*(z001-z101)
                     + (bx011+bx111+bx101)*(z011-z111)
                     - (bx000+bx100+bx110)*(z000-z100)
                     - (bx010+bx110+bx100)*(z010-z110) )
          + (DX/6.f)*( (by101+by111+by011)*(z101-z111)
                     + (by001+by011+by111)*(z001-z011)
                     - (by100+by110+by010)*(z100-z110)
                     - (by000+by010+by110)*(z000-z010) );
        float bxc = 0.125f*(bx000+bx001+bx010+bx011+bx100+bx101+bx110+bx111);
        float byc = 0.125f*(by000+by001+by010+by011+by100+by101+by110+by111);
        float bzc = 0.125f*(bz000+bz001+bz010+bz011+bz100+bz101+bz110+bz111);
        float den = bxc*bxc + byc*byc + bzc*bzc + 1e-10f;
        s_div += __fdividef(num*num, den);
    };

    if (i < NI - 1 && j < NJ - 1) {            // warp-uniform branch
        // cell at k = 2*lane
        cell(BX00.x, BX00.y, BX01.x, BX01.y, BX10.x, BX10.y, BX11.x, BX11.y,
             BY00.x, BY00.y, BY01.x, BY01.y, BY10.x, BY10.y, BY11.x, BY11.y,
             BZ00.x, BZ00.y, BZ01.x, BZ01.y, BZ10.x, BZ10.y, BZ11.x, BZ11.y,
             Z00.x,  Z00.y,  Z01.x,  Z01.y,  Z10.x,  Z10.y,  Z11.x,  Z11.y);
        // cell at k = 2*lane+1 (invalid only at lane 31 -> k=63)
        if (lane < 31) {
            cell(BX00.y, nbx00, BX01.y, nbx01, BX10.y, nbx10, BX11.y, nbx11,
                 BY00.y, nby00, BY01.y, nby01, BY10.y, nby10, BY11.y, nby11,
                 BZ00.y, nbz00, BZ01.y, nbz01, BZ10.y, nbz10, BZ11.y, nbz11,
                 Z00.y,  nz00,  Z01.y,  nz01,  Z10.y,  nz10,  Z11.y,  nz11);
        }
    }

    // ---- reduction: warp -> shared -> block -> global(double) ----
    #pragma unroll
    for (int o = 16; o; o >>= 1) {
        s_bxy += __shfl_down_sync(FULL, s_bxy, o);
        s_bz  += __shfl_down_sync(FULL, s_bz,  o);
        s_par += __shfl_down_sync(FULL, s_par, o);
        s_div += __shfl_down_sync(FULL, s_div, o);
    }
    __shared__ float sh[4][8];
    const int w = threadIdx.x >> 5;
    if (lane == 0) { sh[0][w]=s_bxy; sh[1][w]=s_bz; sh[2][w]=s_par; sh[3][w]=s_div; }
    __syncthreads();
    if (threadIdx.x < 4) {
        float s = 0.f;
        #pragma unroll
        for (int q = 0; q < 8; q++) s += sh[threadIdx.x][q];
        atomicAdd(&g_acc[threadIdx.x], (double)s);
    }
    __syncthreads();

    // ---- grid-wide finalize (last block to arrive) ----
    if (threadIdx.x == 0) {
        __threadfence();
        const unsigned ticket = atomicAdd(&g_cnt, 1u);
        if (ticket == GRID - 1) {
            __threadfence();   // all g_acc atomics now visible
            const double lb = g_acc[0] / NPIX + g_acc[1] / NPIX;
            const double lp = g_acc[2] / NPIX;
            out[0] = (float)(1000.0 * lb + 1000.0 * lp);
            out[1] = (float)(100.0 * (g_acc[3] / NCELL) * 1.0e4); // / DX^2 / DY^2
            // reset for next graph replay
            g_acc[0] = 0.0; g_acc[1] = 0.0; g_acc[2] = 0.0; g_acc[3] = 0.0;
            g_cnt = 0u;
            __threadfence();
        }
    }
}

extern "C" void kernel_launch(void* const* d_in, const int* in_sizes, int n_in,
                              void* d_out, int out_size)
{
    const float* outputs = (const float*)d_in[0];
    const float* targets = (const float*)d_in[1];
    if (n_in >= 2 && in_sizes[0] == 4 * NB * CVOL && in_sizes[1] == 3 * NB * CVOL) {
        const float* t = outputs; outputs = targets; targets = t;
    }
    loss_kernel<<<GRID, 256>>>(outputs, targets, (float*)d_out);
}

// round 5
// speedup vs baseline: 1.4665x; 1.0914x over previous
#include <cuda_runtime.h>

// Problem geometry
#define NB   2
#define NI   256
#define NJ   256
#define NK   64
#define CVOL (NI*NJ*NK)                       // 4,194,304 per (batch,channel)
#define NPIX ((double)NB*CVOL)                // 8,388,608
#define NCELL ((double)NB*255.0*255.0*63.0)   // cells
#define GRID 16384

__device__ double g_acc[4];   // zero at module load; finalize resets after use

// ---------------- packed fp32x2 helpers (sm_103a FFMA2 path) ----------------
typedef unsigned long long u64;

__device__ __forceinline__ u64 pk2(float lo, float hi) {
    u64 r; asm("mov.b64 %0, {%1, %2};" : "=l"(r) : "f"(lo), "f"(hi)); return r;
}
__device__ __forceinline__ u64 f2p(float2 v) { return pk2(v.x, v.y); }
__device__ __forceinline__ void upk2(u64 v, float& a, float& b) {
    asm("mov.b64 {%0, %1}, %2;" : "=f"(a), "=f"(b) : "l"(v));
}
__device__ __forceinline__ u64 add2(u64 a, u64 b) {
    u64 r; asm("add.rn.f32x2 %0, %1, %2;" : "=l"(r) : "l"(a), "l"(b)); return r;
}
__device__ __forceinline__ u64 sub2(u64 a, u64 b) {
    u64 r; asm("sub.rn.f32x2 %0, %1, %2;" : "=l"(r) : "l"(a), "l"(b)); return r;
}
__device__ __forceinline__ u64 mul2(u64 a, u64 b) {
    u64 r; asm("mul.rn.f32x2 %0, %1, %2;" : "=l"(r) : "l"(a), "l"(b)); return r;
}
__device__ __forceinline__ u64 fma2(u64 a, u64 b, u64 c) {
    u64 r; asm("fma.rn.f32x2 %0, %1, %2, %3;" : "=l"(r) : "l"(a), "l"(b), "l"(c)); return r;
}

__global__ void __launch_bounds__(256, 3)
loss_kernel(const float* __restrict__ O, const float* __restrict__ T)
{
    const int tid  = blockIdx.x * 256 + threadIdx.x;
    const int lane = tid & 31;
    const int row  = tid >> 5;            // 131072 rows = 2*256*256
    const int b    = row >> 16;
    const int ij   = row & 65535;
    const int i    = ij >> 8;
    const int j    = ij & 255;

    const int base = (ij << 6) + (lane << 1);          // (i*256+j)*64 + 2*lane
    const float* __restrict__ Ob = O + b * (3 * CVOL);
    const float* __restrict__ Tb = T + b * (4 * CVOL);

    // clamped corner offsets (loads stay in-bounds; contribution gated below)
    const int io = (i < NI - 1) ? (NJ * NK) : 0;
    const int jo = (j < NJ - 1) ? NK : 0;

    // ---- front-batched loads: 19 x LDG.64 per thread ----
    const float2 BX00 = *(const float2*)(Ob + base);
    const float2 BX10 = *(const float2*)(Ob + base + io);
    const float2 BX01 = *(const float2*)(Ob + base + jo);
    const float2 BX11 = *(const float2*)(Ob + base + io + jo);

    const float2 BY00 = *(const float2*)(Ob + CVOL + base);
    const float2 BY10 = *(const float2*)(Ob + CVOL + base + io);
    const float2 BY01 = *(const float2*)(Ob + CVOL + base + jo);
    const float2 BY11 = *(const float2*)(Ob + CVOL + base + io + jo);

    const float2 BZ00 = *(const float2*)(Ob + 2*CVOL + base);
    const float2 BZ10 = *(const float2*)(Ob + 2*CVOL + base + io);
    const float2 BZ01 = *(const float2*)(Ob + 2*CVOL + base + jo);
    const float2 BZ11 = *(const float2*)(Ob + 2*CVOL + base + io + jo);

    const float2 Z00  = *(const float2*)(Tb + 3*CVOL + base);
    const float2 Z10  = *(const float2*)(Tb + 3*CVOL + base + io);
    const float2 Z01  = *(const float2*)(Tb + 3*CVOL + base + jo);
    const float2 Z11  = *(const float2*)(Tb + 3*CVOL + base + io + jo);

    const float2 TX   = *(const float2*)(Tb + base);
    const float2 TY   = *(const float2*)(Tb + CVOL + base);
    const float2 TZ   = *(const float2*)(Tb + 2*CVOL + base);

    // ---- batched warp-internal k+2 halos (scalar shuffles) ----
    const unsigned FULL = 0xffffffffu;
    const float nbx00 = __shfl_down_sync(FULL, BX00.x, 1);
    const float nbx10 = __shfl_down_sync(FULL, BX10.x, 1);
    const float nbx01 = __shfl_down_sync(FULL, BX01.x, 1);
    const float nbx11 = __shfl_down_sync(FULL, BX11.x, 1);
    const float nby00 = __shfl_down_sync(FULL, BY00.x, 1);
    const float nby10 = __shfl_down_sync(FULL, BY10.x, 1);
    const float nby01 = __shfl_down_sync(FULL, BY01.x, 1);
    const float nby11 = __shfl_down_sync(FULL, BY11.x, 1);
    const float nbz00 = __shfl_down_sync(FULL, BZ00.x, 1);
    const float nbz10 = __shfl_down_sync(FULL, BZ10.x, 1);
    const float nbz01 = __shfl_down_sync(FULL, BZ01.x, 1);
    const float nbz11 = __shfl_down_sync(FULL, BZ11.x, 1);
    const float nz00  = __shfl_down_sync(FULL, Z00.x, 1);
    const float nz10  = __shfl_down_sync(FULL, Z10.x, 1);
    const float nz01  = __shfl_down_sync(FULL, Z01.x, 1);
    const float nz11  = __shfl_down_sync(FULL, Z11.x, 1);

    const u64 EPS2 = pk2(1e-10f, 1e-10f);

    float s_bxy = 0.f, s_bz = 0.f, s_par = 0.f, s_div = 0.f;

    // ================= element-wise losses (both k packed in f32x2) ========
    {
        const u64 bxp = f2p(BX00), byp = f2p(BY00), bzp = f2p(BZ00);
        const u64 bxt = f2p(TX),   byt = f2p(TY),   bzt = f2p(TZ);
        const u64 bxt2 = mul2(bxt, bxt);
        const u64 byt2 = mul2(byt, byt);
        const u64 bzt2 = mul2(bzt, bzt);
        const u64 st   = add2(bxt2, byt2);

        const u64 t   = sub2(fma2(bxp, bxp, mul2(byp, byp)), st);
        const u64 t2  = mul2(t, t);
        const u64 dn1 = add2(st, EPS2);

        const u64 dz  = sub2(bzp, bzt);
        const u64 dz2 = mul2(dz, dz);
        const u64 dz4 = mul2(dz2, dz2);
        const u64 dn2 = add2(bzt2, EPS2);

        const u64 cr  = sub2(mul2(bxp, byt), mul2(byp, bxt));
        const u64 cr2 = mul2(cr, cr);
        const u64 dn3 = add2(add2(st, bzt2), EPS2);

        float na, nb, da, db;
        upk2(t2, na, nb);  upk2(dn1, da, db);
        s_bxy = __fdividef(na, da) + __fdividef(nb, db);
        upk2(dz4, na, nb); upk2(dn2, da, db);
        s_bz  = __fdividef(na, da) + __fdividef(nb, db);
        upk2(cr2, na, nb); upk2(dn3, da, db);
        s_par = __fdividef(na, da) + __fdividef(nb, db);
    }

    // ================= divergence: two cells in one packed pass ============
    if (i < NI - 1 && j < NJ - 1) {            // warp-uniform branch
        // _a = dk0 pair (cell0 uses k, cell1 uses k+1)  -> loaded float2
        // _b = dk1 pair (cell0 uses k+1, cell1 uses k+2) -> (y, shuffled)
        const u64 bx00a = f2p(BX00), bx00b = pk2(BX00.y, nbx00);
        const u64 bx01a = f2p(BX01), bx01b = pk2(BX01.y, nbx01);
        const u64 bx10a = f2p(BX10), bx10b = pk2(BX10.y, nbx10);
        const u64 bx11a = f2p(BX11), bx11b = pk2(BX11.y, nbx11);
        const u64 by00a = f2p(BY00), by00b = pk2(BY00.y, nby00);
        const u64 by01a = f2p(BY01), by01b = pk2(BY01.y, nby01);
        const u64 by10a = f2p(BY10), by10b = pk2(BY10.y, nby10);
        const u64 by11a = f2p(BY11), by11b = pk2(BY11.y, nby11);
        const u64 bz00a = f2p(BZ00), bz00b = pk2(BZ00.y, nbz00);
        const u64 bz01a = f2p(BZ01), bz01b = pk2(BZ01.y, nbz01);
        const u64 bz10a = f2p(BZ10), bz10b = pk2(BZ10.y, nbz10);
        const u64 bz11a = f2p(BZ11), bz11b = pk2(BZ11.y, nbz11);
        const u64 z00a  = f2p(Z00),  z00b  = pk2(Z00.y, nz00);
        const u64 z01a  = f2p(Z01),  z01b  = pk2(Z01.y, nz01);
        const u64 z10a  = f2p(Z10),  z10b  = pk2(Z10.y, nz10);
        const u64 z11a  = f2p(Z11),  z11b  = pk2(Z11.y, nz11);

        // face-flux terms (0.125*DY and 0.125*DX both = 0.0125)
        const u64 sxp = add2(add2(bx10a, bx11a), add2(bx10b, bx11b));
        const u64 sxm = add2(add2(bx00a, bx01a), add2(bx00b, bx01b));
        const u64 dxp = add2(sub2(z10b, z10a), sub2(z11b, z11a));
        const u64 dxm = add2(sub2(z00b, z00a), sub2(z01b, z01a));
        const u64 termx = sub2(mul2(sxp, dxp), mul2(sxm, dxm));

        const u64 syp = add2(add2(by01a, by11a), add2(by01b, by11b));
        const u64 sym = add2(add2(by00a, by10a), add2(by00b, by10b));
        const u64 dyp = add2(sub2(z01b, z01a), sub2(z11b, z11a));
        const u64 dym = add2(sub2(z00b, z00a), sub2(z10b, z10a));
        const u64 termy = sub2(mul2(syp, dyp), mul2(sym, dym));

        const u64 termz = sub2(add2(add2(bz00b, bz01b), add2(bz10b, bz11b)),
                               add2(add2(bz00a, bz01a), add2(bz10a, bz11a)));

        // triangle terms ((DY/6)=(DX/6))
        const u64 tx1 = mul2(add2(add2(bx00b, bx10b), bx11b), sub2(z00b, z10b));
        const u64 tx2 = mul2(add2(add2(bx01b, bx11b), bx10b), sub2(z01b, z11b));
        const u64 tx3 = mul2(add2(add2(bx00a, bx10a), bx11a), sub2(z00a, z10a));
        const u64 tx4 = mul2(add2(add2(bx01a, bx11a), bx10a), sub2(z01a, z11a));
        const u64 trix = sub2(add2(tx1, tx2), add2(tx3, tx4));

        const u64 ty1 = mul2(add2(add2(by10b, by11b), by01b), sub2(z10b, z11b));
        const u64 ty2 = mul2(add2(add2(by00b, by01b), by11b), sub2(z00b, z01b));
        const u64 ty3 = mul2(add2(add2(by10a, by11a), by01a), sub2(z10a, z11a));
        const u64 ty4 = mul2(add2(add2(by00a, by01a), by11a), sub2(z00a, z01a));
        const u64 triy = sub2(add2(ty1, ty2), add2(ty3, ty4));

        const u64 C0125 = pk2(0.0125f, 0.0125f);        // 0.125 * 0.1
        const u64 C0025 = pk2(0.0025f, 0.0025f);        // 0.25 * 0.1 * 0.1
        const u64 C6    = pk2(0.1f/6.f, 0.1f/6.f);      // DX/6 = DY/6
        const u64 num = fma2(C0125, add2(termx, termy),
                        fma2(C0025, termz,
                        mul2(C6, add2(trix, triy))));

        // cell centers
        const u64 C8 = pk2(0.125f, 0.125f);
        const u64 bxc = mul2(C8, add2(add2(add2(bx00a, bx01a), add2(bx10a, bx11a)),
                                      add2(add2(bx00b, bx01b), add2(bx10b, bx11b))));
        const u64 byc = mul2(C8, add2(add2(add2(by00a, by01a), add2(by10a, by11a)),
                                      add2(add2(by00b, by01b), add2(by10b, by11b))));
        const u64 bzc = mul2(C8, add2(add2(add2(bz00a, bz01a), add2(bz10a, bz11a)),
                                      add2(add2(bz00b, bz01b), add2(bz10b, bz11b))));
        const u64 den  = add2(fma2(bxc, bxc, fma2(byc, byc, mul2(bzc, bzc))), EPS2);
        const u64 num2 = mul2(num, num);

        float n0, n1, d0, d1;
        upk2(num2, n0, n1);
        upk2(den,  d0, d1);
        s_div = __fdividef(n0, d0);
        if (lane < 31) s_div += __fdividef(n1, d1);     // cell1 invalid at k=63
    }

    // ================= reduction (packed pairs) ============================
    u64 p1 = pk2(s_bxy, s_bz);
    u64 p2 = pk2(s_par, s_div);
    #pragma unroll
    for (int o = 16; o; o >>= 1) {
        p1 = add2(p1, __shfl_down_sync(FULL, p1, o));
        p2 = add2(p2, __shfl_down_sync(FULL, p2, o));
    }
    __shared__ float sh[4][8];
    const int w = threadIdx.x >> 5;
    if (lane == 0) {
        float a, b2, c, d;
        upk2(p1, a, b2); upk2(p2, c, d);
        sh[0][w] = a; sh[1][w] = b2; sh[2][w] = c; sh[3][w] = d;
    }
    __syncthreads();
    if (threadIdx.x < 4) {
        float s = 0.f;
        #pragma unroll
        for (int q = 0; q < 8; q++) s += sh[threadIdx.x][q];
        atomicAdd(&g_acc[threadIdx.x], (double)s);
    }
}

__global__ void finalize_kernel(float* __restrict__ out)
{
    const double lb = g_acc[0] / NPIX + g_acc[1] / NPIX;
    const double lp = g_acc[2] / NPIX;
    out[0] = (float)(1000.0 * lb + 1000.0 * lp);
    out[1] = (float)(100.0 * (g_acc[3] / NCELL) * 1.0e4);  // / DX^2 / DY^2
    // reset for the next graph replay (g_acc starts zero at module load)
    g_acc[0] = 0.0; g_acc[1] = 0.0; g_acc[2] = 0.0; g_acc[3] = 0.0;
}

extern "C" void kernel_launch(void* const* d_in, const int* in_sizes, int n_in,
                              void* d_out, int out_size)
{
    const float* outputs = (const float*)d_in[0];
    const float* targets = (const float*)d_in[1];
    if (n_in >= 2 && in_sizes[0] == 4 * NB * CVOL && in_sizes[1] == 3 * NB * CVOL) {
        const float* t = outputs; outputs = targets; targets = t;
    }
    loss_kernel<<<GRID, 256>>>(outputs, targets);
    finalize_kernel<<<1, 1>>>((float*)d_out);
}

// round 10
// speedup vs baseline: 1.5930x; 1.0862x over previous
#include <cuda_runtime.h>

// Problem geometry
#define NB   2
#define NI   256
#define NJ   256
#define NK   64
#define CVOL (NI*NJ*NK)                       // 4,194,304 per (batch,channel)
#define NPIX ((double)NB*CVOL)                // 8,388,608
#define NCELL ((double)NB*255.0*255.0*63.0)   // cells
#define GRID 8192

__device__ double g_acc[4];   // zero at module load; finalize resets after use

// ---------------- packed fp32x2 helpers (sm_103a FFMA2 path) ----------------
typedef unsigned long long u64;

__device__ __forceinline__ u64 pk2(float lo, float hi) {
    u64 r; asm("mov.b64 %0, {%1, %2};" : "=l"(r) : "f"(lo), "f"(hi)); return r;
}
__device__ __forceinline__ void upk2(u64 v, float& a, float& b) {
    asm("mov.b64 {%0, %1}, %2;" : "=f"(a), "=f"(b) : "l"(v));
}
__device__ __forceinline__ u64 add2(u64 a, u64 b) {
    u64 r; asm("add.rn.f32x2 %0, %1, %2;" : "=l"(r) : "l"(a), "l"(b)); return r;
}
__device__ __forceinline__ u64 sub2(u64 a, u64 b) {
    u64 r; asm("sub.rn.f32x2 %0, %1, %2;" : "=l"(r) : "l"(a), "l"(b)); return r;
}
__device__ __forceinline__ u64 mul2(u64 a, u64 b) {
    u64 r; asm("mul.rn.f32x2 %0, %1, %2;" : "=l"(r) : "l"(a), "l"(b)); return r;
}
__device__ __forceinline__ u64 fma2(u64 a, u64 b, u64 c) {
    u64 r; asm("fma.rn.f32x2 %0, %1, %2, %3;" : "=l"(r) : "l"(a), "l"(b), "l"(c)); return r;
}

__global__ void __launch_bounds__(256, 2)
loss_kernel(const float* __restrict__ O, const float* __restrict__ T)
{
    const int tid  = blockIdx.x * 256 + threadIdx.x;
    const int lane = threadIdx.x & 31;
    const int hl   = lane & 15;          // lane within half-warp
    const int half = lane >> 4;          // batch index b
    const int w    = tid >> 5;           // 65536 warps = 256*256 (i,j) rows
    const int i    = w >> 8;
    const int j    = w & 255;

    const int base = (w << 6) + (hl << 2);     // (i*256+j)*64 + 4*hl
    const float* __restrict__ Obl = O + half * (3 * CVOL);
    const float* __restrict__ Tbl = T + half * (4 * CVOL);

    // clamped corner offsets (warp-uniform; contribution gated below)
    const int io = (i < NI - 1) ? (NJ * NK) : 0;
    const int jo = (j < NJ - 1) ? NK : 0;
    const int off0 = 0, off1 = jo, off2 = io, off3 = io + jo;

    // ---- front-batched loads: 19 x LDG.128 per thread (serves 2 rows/warp) ----
    float4 CBX[4], CBY[4], CBZ[4], CZ[4];
    CBX[0] = *(const float4*)(Obl + base + off0);
    CBX[1] = *(const float4*)(Obl + base + off1);
    CBX[2] = *(const float4*)(Obl + base + off2);
    CBX[3] = *(const float4*)(Obl + base + off3);
    CBY[0] = *(const float4*)(Obl + CVOL + base + off0);
    CBY[1] = *(const float4*)(Obl + CVOL + base + off1);
    CBY[2] = *(const float4*)(Obl + CVOL + base + off2);
    CBY[3] = *(const float4*)(Obl + CVOL + base + off3);
    CBZ[0] = *(const float4*)(Obl + 2*CVOL + base + off0);
    CBZ[1] = *(const float4*)(Obl + 2*CVOL + base + off1);
    CBZ[2] = *(const float4*)(Obl + 2*CVOL + base + off2);
    CBZ[3] = *(const float4*)(Obl + 2*CVOL + base + off3);
    CZ[0]  = *(const float4*)(Tbl + 3*CVOL + base + off0);
    CZ[1]  = *(const float4*)(Tbl + 3*CVOL + base + off1);
    CZ[2]  = *(const float4*)(Tbl + 3*CVOL + base + off2);
    CZ[3]  = *(const float4*)(Tbl + 3*CVOL + base + off3);
    const float4 TXv = *(const float4*)(Tbl + base);
    const float4 TYv = *(const float4*)(Tbl + CVOL + base);
    const float4 TZv = *(const float4*)(Tbl + 2*CVOL + base);

    // ---- k+4 halo: shuffled .x from lane+1 (cross-half garbage gated) ----
    const unsigned FULL = 0xffffffffu;
    float SBX[4], SBY[4], SBZ[4], SZ[4];
    #pragma unroll
    for (int c = 0; c < 4; c++) {
        SBX[c] = __shfl_down_sync(FULL, CBX[c].x, 1);
        SBY[c] = __shfl_down_sync(FULL, CBY[c].x, 1);
        SBZ[c] = __shfl_down_sync(FULL, CBZ[c].x, 1);
        SZ[c]  = __shfl_down_sync(FULL, CZ[c].x, 1);
    }

    const u64 EPS2 = pk2(1e-10f, 1e-10f);

    float s_bxy = 0.f, s_bz = 0.f, s_par = 0.f, s_div = 0.f;

    // ================= element-wise losses: 4 k-values = 2 packed passes ====
    #pragma unroll
    for (int e = 0; e < 2; e++) {
        const u64 bxp = e ? pk2(CBX[0].z, CBX[0].w) : pk2(CBX[0].x, CBX[0].y);
        const u64 byp = e ? pk2(CBY[0].z, CBY[0].w) : pk2(CBY[0].x, CBY[0].y);
        const u64 bzp = e ? pk2(CBZ[0].z, CBZ[0].w) : pk2(CBZ[0].x, CBZ[0].y);
        const u64 bxt = e ? pk2(TXv.z, TXv.w) : pk2(TXv.x, TXv.y);
        const u64 byt = e ? pk2(TYv.z, TYv.w) : pk2(TYv.x, TYv.y);
        const u64 bzt = e ? pk2(TZv.z, TZv.w) : pk2(TZv.x, TZv.y);

        const u64 bxt2 = mul2(bxt, bxt);
        const u64 byt2 = mul2(byt, byt);
        const u64 bzt2 = mul2(bzt, bzt);
        const u64 st   = add2(bxt2, byt2);

        const u64 t   = sub2(fma2(bxp, bxp, mul2(byp, byp)), st);
        const u64 t2  = mul2(t, t);
        const u64 dn1 = add2(st, EPS2);

        const u64 dz  = sub2(bzp, bzt);
        const u64 dz2 = mul2(dz, dz);
        const u64 dz4 = mul2(dz2, dz2);
        const u64 dn2 = add2(bzt2, EPS2);

        const u64 cr  = sub2(mul2(bxp, byt), mul2(byp, bxt));
        const u64 cr2 = mul2(cr, cr);
        const u64 dn3 = add2(add2(st, bzt2), EPS2);

        float na, nb, da, db;
        upk2(t2, na, nb);  upk2(dn1, da, db);
        s_bxy += __fdividef(na*db + nb*da, da*db);
        upk2(dz4, na, nb); upk2(dn2, da, db);
        s_bz  += __fdividef(na*db + nb*da, da*db);
        upk2(cr2, na, nb); upk2(dn3, da, db);
        s_par += __fdividef(na*db + nb*da, da*db);
    }

    // ================= divergence: 4 cells = 2 packed passes ================
    if (i < NI - 1 && j < NJ - 1) {            // warp-uniform branch
        #pragma unroll
        for (int p = 0; p < 2; p++) {
            // a = dk0 corner pair, b = dk1 corner pair for cells (4hl+2p, 4hl+2p+1)
            u64 bxa[4], bxb[4], bya[4], byb[4], bza[4], bzb[4], za[4], zb[4];
            #pragma unroll
            for (int c = 0; c < 4; c++) {
                bxa[c] = p ? pk2(CBX[c].z, CBX[c].w) : pk2(CBX[c].x, CBX[c].y);
                bxb[c] = p ? pk2(CBX[c].w, SBX[c])   : pk2(CBX[c].y, CBX[c].z);
                bya[c] = p ? pk2(CBY[c].z, CBY[c].w) : pk2(CBY[c].x, CBY[c].y);
                byb[c] = p ? pk2(CBY[c].w, SBY[c])   : pk2(CBY[c].y, CBY[c].z);
                bza[c] = p ? pk2(CBZ[c].z, CBZ[c].w) : pk2(CBZ[c].x, CBZ[c].y);
                bzb[c] = p ? pk2(CBZ[c].w, SBZ[c])   : pk2(CBZ[c].y, CBZ[c].z);
                za[c]  = p ? pk2(CZ[c].z,  CZ[c].w)  : pk2(CZ[c].x,  CZ[c].y);
                zb[c]  = p ? pk2(CZ[c].w,  SZ[c])    : pk2(CZ[c].y,  CZ[c].z);
            }

            // face-flux terms
            const u64 sxp = add2(add2(bxa[2], bxa[3]), add2(bxb[2], bxb[3]));
            const u64 sxm = add2(add2(bxa[0], bxa[1]), add2(bxb[0], bxb[1]));
            const u64 dxp = add2(sub2(zb[2], za[2]), sub2(zb[3], za[3]));
            const u64 dxm = add2(sub2(zb[0], za[0]), sub2(zb[1], za[1]));
            const u64 termx = sub2(mul2(sxp, dxp), mul2(sxm, dxm));

            const u64 syp = add2(add2(bya[1], bya[3]), add2(byb[1], byb[3]));
            const u64 sym = add2(add2(bya[0], bya[2]), add2(byb[0], byb[2]));
            const u64 dyp = add2(sub2(zb[1], za[1]), sub2(zb[3], za[3]));
            const u64 dym = add2(sub2(zb[0], za[0]), sub2(zb[2], za[2]));
            const u64 termy = sub2(mul2(syp, dyp), mul2(sym, dym));

            const u64 termz = sub2(add2(add2(bzb[0], bzb[1]), add2(bzb[2], bzb[3])),
                                   add2(add2(bza[0], bza[1]), add2(bza[2], bza[3])));

            // triangle terms
            const u64 tx1 = mul2(add2(add2(bxb[0], bxb[2]), bxb[3]), sub2(zb[0], zb[2]));
            const u64 tx2 = mul2(add2(add2(bxb[1], bxb[3]), bxb[2]), sub2(zb[1], zb[3]));
            const u64 tx3 = mul2(add2(add2(bxa[0], bxa[2]), bxa[3]), sub2(za[0], za[2]));
            const u64 tx4 = mul2(add2(add2(bxa[1], bxa[3]), bxa[2]), sub2(za[1], za[3]));
            const u64 trix = sub2(add2(tx1, tx2), add2(tx3, tx4));

            const u64 ty1 = mul2(add2(add2(byb[2], byb[3]), byb[1]), sub2(zb[2], zb[3]));
            const u64 ty2 = mul2(add2(add2(byb[0], byb[1]), byb[3]), sub2(zb[0], zb[1]));
            const u64 ty3 = mul2(add2(add2(bya[2], bya[3]), bya[1]), sub2(za[2], za[3]));
            const u64 ty4 = mul2(add2(add2(bya[0], bya[1]), bya[3]), sub2(za[0], za[1]));
            const u64 triy = sub2(add2(ty1, ty2), add2(ty3, ty4));

            const u64 C0125 = pk2(0.0125f, 0.0125f);        // 0.125 * 0.1
            const u64 C0025 = pk2(0.0025f, 0.0025f);        // 0.25 * 0.1 * 0.1
            const u64 C6    = pk2(0.1f/6.f, 0.1f/6.f);      // DX/6 = DY/6
            const u64 num = fma2(C0125, add2(termx, termy),
                            fma2(C0025, termz,
                            mul2(C6, add2(trix, triy))));

            // cell centers
            const u64 C8 = pk2(0.125f, 0.125f);
            const u64 bxc = mul2(C8, add2(add2(add2(bxa[0], bxa[1]), add2(bxa[2], bxa[3])),
                                          add2(add2(bxb[0], bxb[1]), add2(bxb[2], bxb[3]))));
            const u64 byc = mul2(C8, add2(add2(add2(bya[0], bya[1]), add2(bya[2], bya[3])),
                                          add2(add2(byb[0], byb[1]), add2(byb[2], byb[3]))));
            const u64 bzc = mul2(C8, add2(add2(add2(bza[0], bza[1]), add2(bza[2], bza[3])),
                                          add2(add2(bzb[0], bzb[1]), add2(bzb[2], bzb[3]))));
            const u64 den  = add2(fma2(bxc, bxc, fma2(byc, byc, mul2(bzc, bzc))), EPS2);
            const u64 num2 = mul2(num, num);

            float n0, n1, d0, d1;
            upk2(num2, n0, n1);
            upk2(den,  d0, d1);
            if (p == 1 && hl == 15) { n1 = 0.f; d1 = 1.0f; }  // cell k=63 invalid
            s_div += __fdividef(n0*d1 + n1*d0, d0*d1);
        }
    }

    // ================= reduction (packed pairs) ============================
    u64 p1 = pk2(s_bxy, s_bz);
    u64 p2 = pk2(s_par, s_div);
    #pragma unroll
    for (int o = 16; o; o >>= 1) {
        p1 = add2(p1, __shfl_down_sync(FULL, p1, o));
        p2 = add2(p2, __shfl_down_sync(FULL, p2, o));
    }
    __shared__ float sh[4][8];
    const int wb = threadIdx.x >> 5;
    if (lane == 0) {
        float a, b2, c, d;
        upk2(p1, a, b2); upk2(p2, c, d);
        sh[0][wb] = a; sh[1][wb] = b2; sh[2][wb] = c; sh[3][wb] = d;
    }
    __syncthreads();
    if (threadIdx.x < 4) {
        float s = 0.f;
        #pragma unroll
        for (int q = 0; q < 8; q++) s += sh[threadIdx.x][q];
        atomicAdd(&g_acc[threadIdx.x], (double)s);
    }
}

__global__ void finalize_kernel(float* __restrict__ out)
{
    const double lb = g_acc[0] / NPIX + g_acc[1] / NPIX;
    const double lp = g_acc[2] / NPIX;
    out[0] = (float)(1000.0 * lb + 1000.0 * lp);
    out[1] = (float)(100.0 * (g_acc[3] / NCELL) * 1.0e4);  // / DX^2 / DY^2
    // reset for the next graph replay (g_acc starts zero at module load)
    g_acc[0] = 0.0; g_acc[1] = 0.0; g_acc[2] = 0.0; g_acc[3] = 0.0;
}

extern "C" void kernel_launch(void* const* d_in, const int* in_sizes, int n_in,
                              void* d_out, int out_size)
{
    const float* outputs = (const float*)d_in[0];
    const float* targets = (const float*)d_in[1];
    if (n_in >= 2 && in_sizes[0] == 4 * NB * CVOL && in_sizes[1] == 3 * NB * CVOL) {
        const float* t = outputs; outputs = targets; targets = t;
    }
    loss_kernel<<<GRID, 256>>>(outputs, targets);
    finalize_kernel<<<1, 1>>>((float*)d_out);
}